// round 4
// baseline (speedup 1.0000x reference)
#include <cuda_runtime.h>

#define NIMG 800

// ---------------- scratch (no allocation allowed) ----------------
__device__ float  g_buf1[NIMG * 4 * 30 * 30];   // conv1 pooled output (NCHW)
__device__ float  g_buf2[NIMG * 8 * 25];        // conv2 pooled output (NCHW)
__device__ float  g_z[NIMG * 2];
__device__ float  g_L[NIMG * 3];
__device__ double g_stats[24];

__global__ void k_zero() { if (threadIdx.x < 24) g_stats[threadIdx.x] = 0.0; }

// ---- f32x2 packed-math helpers ----
__device__ __forceinline__ unsigned long long ffma2(unsigned long long a,
                                                    unsigned long long b,
                                                    unsigned long long c) {
    unsigned long long d;
    asm("fma.rn.f32x2 %0, %1, %2, %3;" : "=l"(d) : "l"(a), "l"(b), "l"(c));
    return d;
}
__device__ __forceinline__ unsigned long long packbc(float x) {  // (x, x)
    unsigned long long d;
    asm("mov.b64 %0, {%1, %2};" : "=l"(d) : "f"(x), "f"(x));
    return d;
}
__device__ __forceinline__ void unpack2(unsigned long long v, float& lo, float& hi) {
    asm("mov.b64 {%0, %1}, %2;" : "=f"(lo), "=f"(hi) : "l"(v));
}

// ---------------- conv1 + bias + relu + maxpool2 + bn1-stats ----------------
// Block: one image, 10 pooled rows. Thread: horizontal pooled PAIR (pw=2p,2p+1), all 4 oc.
// Dynamic smem: planar [3][47][ROWSTRIDE] with 16B pad every 8 chunks (bank de-conflict).
#define C1_ROWS 47
#define C1_RS   148          // padded row stride in floats (33 chunks + 4 pad chunks)
#define C1_PLANE 6960        // 47*148=6956 rounded
#define C1_DSM  (3 * C1_PLANE * 4)

__global__ __launch_bounds__(160, 2) void k_conv1(
    const float* __restrict__ x, const float* __restrict__ cw,
    const float* __restrict__ cb)
{
    extern __shared__ __align__(16) float dsm[];
    __shared__ __align__(16) float sm_w[972];   // [ic][kh][kw][oc]
    __shared__ float sm_b[4];
    __shared__ float s_part[5][8];
    const int tid = threadIdx.x;
    const int n   = blockIdx.y;
    const int bx  = blockIdx.x;           // 0..2 -> pooled rows 10*bx..10*bx+9

    if (tid < 4) sm_b[tid] = cb[tid];
    for (int i = tid; i < 972; i += 160) {
        int oc = i & 3; int rest = i >> 2;
        int kw = rest % 9; int t2 = rest / 9; int kh = t2 % 9; int ic = t2 / 9;
        sm_w[i] = cw[oc * 243 + ic * 81 + kh * 9 + kw];
    }
    // stage 47 input rows (NHWC -> planar, padded-chunk layout)
    const float4* xb = (const float4*)(x + (size_t)n * 49152 + (size_t)(40 * bx) * 384);
    for (int i = tid; i < C1_ROWS * 32; i += 160) {
        int row = i >> 5; int g = i & 31;
        const float4* src = xb + row * 96 + g * 3;
        float4 a = src[0], b = src[1], c = src[2];
        int off = row * C1_RS + 4 * g + ((g >> 3) << 2);
        *(float4*)(dsm + off)                = make_float4(a.x, a.w, b.z, c.y);
        *(float4*)(dsm + C1_PLANE + off)     = make_float4(a.y, b.x, b.w, c.z);
        *(float4*)(dsm + 2 * C1_PLANE + off) = make_float4(a.z, b.y, c.x, c.w);
    }
    __syncthreads();

    const bool valid = (tid < 150);
    const int prow = valid ? (tid / 15) : 0;
    const int p    = valid ? (tid % 15) : 0;
    int colOff[4];
    #pragma unroll
    for (int k = 0; k < 4; k++) {
        int c = 2 * p + k;
        colOff[k] = 4 * c + ((c >> 3) << 2);
    }

    // acc[out][pair][dy][dx], pair0=(oc0,oc1), pair1=(oc2,oc3)
    unsigned long long acc[2][2][2][2];
    #pragma unroll
    for (int o = 0; o < 2; o++)
        #pragma unroll
        for (int q = 0; q < 2; q++)
            #pragma unroll
            for (int dy = 0; dy < 2; dy++) { acc[o][q][dy][0] = 0ull; acc[o][q][dy][1] = 0ull; }

    #pragma unroll 1
    for (int ic = 0; ic < 3; ic++) {
        const float* plane = dsm + ic * C1_PLANE + (4 * prow) * C1_RS;
        const float* wb = sm_w + ic * 324;
        #pragma unroll 1
        for (int kh = 0; kh < 9; kh++) {
            #pragma unroll
            for (int dy = 0; dy < 2; dy++) {
                const float* rp = plane + (kh + 2 * dy) * C1_RS;
                float4 v0 = *(const float4*)(rp + colOff[0]);
                float4 v1 = *(const float4*)(rp + colOff[1]);
                float4 v2 = *(const float4*)(rp + colOff[2]);
                float4 v3 = *(const float4*)(rp + colOff[3]);
                float in[16] = {v0.x, v0.y, v0.z, v0.w, v1.x, v1.y, v1.z, v1.w,
                                v2.x, v2.y, v2.z, v2.w, v3.x, v3.y, v3.z, v3.w};
                unsigned long long bp[15];
                #pragma unroll
                for (int j = 0; j < 15; j++) bp[j] = packbc(in[j]);
                #pragma unroll
                for (int kw = 0; kw < 9; kw++) {
                    ulonglong2 w2 = *(const ulonglong2*)(wb + (kh * 9 + kw) * 4);
                    acc[0][0][dy][0] = ffma2(w2.x, bp[kw],     acc[0][0][dy][0]);
                    acc[0][0][dy][1] = ffma2(w2.x, bp[kw + 2], acc[0][0][dy][1]);
                    acc[0][1][dy][0] = ffma2(w2.y, bp[kw],     acc[0][1][dy][0]);
                    acc[0][1][dy][1] = ffma2(w2.y, bp[kw + 2], acc[0][1][dy][1]);
                    acc[1][0][dy][0] = ffma2(w2.x, bp[kw + 4], acc[1][0][dy][0]);
                    acc[1][0][dy][1] = ffma2(w2.x, bp[kw + 6], acc[1][0][dy][1]);
                    acc[1][1][dy][0] = ffma2(w2.y, bp[kw + 4], acc[1][1][dy][0]);
                    acc[1][1][dy][1] = ffma2(w2.y, bp[kw + 6], acc[1][1][dy][1]);
                }
            }
        }
    }
    // unpack, pool(max over dy,dx), bias, relu, store both pooled cols
    float m[2][4];
    #pragma unroll
    for (int o = 0; o < 2; o++)
        #pragma unroll
        for (int q = 0; q < 2; q++) {
            float l00, h00, l01, h01, l10, h10, l11, h11;
            unpack2(acc[o][q][0][0], l00, h00);
            unpack2(acc[o][q][0][1], l01, h01);
            unpack2(acc[o][q][1][0], l10, h10);
            unpack2(acc[o][q][1][1], l11, h11);
            m[o][2 * q]     = fmaxf(fmaxf(l00, l01), fmaxf(l10, l11));
            m[o][2 * q + 1] = fmaxf(fmaxf(h00, h01), fmaxf(h10, h11));
        }
    const int ph = 10 * bx + prow;
    float vs[4], vq[4];
    #pragma unroll
    for (int oc = 0; oc < 4; oc++) {
        float b  = sm_b[oc];
        float a0 = fmaxf(m[0][oc] + b, 0.f);
        float a1 = fmaxf(m[1][oc] + b, 0.f);
        if (valid)
            *(float2*)(g_buf1 + ((n * 4 + oc) * 30 + ph) * 30 + 2 * p) = make_float2(a0, a1);
        vs[oc] = valid ? (a0 + a1) : 0.f;
        vq[oc] = valid ? (a0 * a0 + a1 * a1) : 0.f;
    }
    #pragma unroll
    for (int oc = 0; oc < 4; oc++)
        #pragma unroll
        for (int off = 16; off > 0; off >>= 1) {
            vs[oc] += __shfl_xor_sync(0xffffffffu, vs[oc], off);
            vq[oc] += __shfl_xor_sync(0xffffffffu, vq[oc], off);
        }
    const int wp = tid >> 5;
    if ((tid & 31) == 0) {
        #pragma unroll
        for (int oc = 0; oc < 4; oc++) {
            s_part[wp][oc]     = vs[oc];
            s_part[wp][4 + oc] = vq[oc];
        }
    }
    __syncthreads();
    if (tid < 8) {
        float t = 0.f;
        #pragma unroll
        for (int w = 0; w < 5; w++) t += s_part[w][tid];
        atomicAdd(&g_stats[tid], (double)t);
    }
}

// ---------------- bn1-apply + conv2 + relu + pool + bn2-stats ----------------
__global__ __launch_bounds__(224) void k_conv2(
    const float* __restrict__ cw, const float* __restrict__ cb,
    const float* __restrict__ g1, const float* __restrict__ b1)
{
    __shared__ __align__(16) float sm_in[4 * 960];
    __shared__ float sm_w[2592];
    __shared__ float sm_b[8];
    __shared__ float sc[4], shh[4];
    __shared__ float s_sum[8], s_sq[8];
    const int tid = threadIdx.x;
    const int n   = blockIdx.x;
    if (tid < 4) {
        double mu  = g_stats[tid] * (1.0 / 720000.0);
        double var = g_stats[4 + tid] * (1.0 / 720000.0) - mu * mu;
        float scale = g1[tid] * rsqrtf((float)var + 1e-5f);
        sc[tid] = scale; shh[tid] = b1[tid] - (float)mu * scale;
    }
    if (tid < 8) { s_sum[tid] = 0.f; s_sq[tid] = 0.f; sm_b[tid] = cb[tid]; }
    __syncthreads();
    for (int i = tid; i < 3600; i += 224) {
        int ic = i / 900; int rem = i - ic * 900;
        int row = rem / 30; int col = rem - row * 30;
        int chunk = col >> 2, within = col & 3;
        int pcol = (((chunk ^ (row & 7)) << 2) | within);
        sm_in[ic * 960 + row * 32 + pcol] = fmaf(g_buf1[n * 3600 + i], sc[ic], shh[ic]);
    }
    for (int i = tid; i < 2592; i += 224) sm_w[i] = cw[i];
    __syncthreads();
    if (tid < 200) {
        const int oc = tid / 25;
        const int p  = tid - oc * 25;
        const int pr = p / 5, pc = p - pr * 5;
        float acc[2][2] = {{0.f, 0.f}, {0.f, 0.f}};
        #pragma unroll 1
        for (int ic = 0; ic < 4; ic++) {
            const float* wb = sm_w + oc * 324 + ic * 81;
            const float* ib = sm_in + ic * 960;
            #pragma unroll 1
            for (int kh = 0; kh < 9; kh++) {
                float w[9];
                #pragma unroll
                for (int kw = 0; kw < 9; kw++) w[kw] = wb[kh * 9 + kw];
                #pragma unroll
                for (int dy = 0; dy < 2; dy++) {
                    const int row = 4 * pr + 2 * dy + kh;
                    const int rb  = row * 32;
                    const int rx  = row & 7;
                    float4 v0 = *(const float4*)(ib + rb + (((pc    ) ^ rx) << 2));
                    float4 v1 = *(const float4*)(ib + rb + (((pc + 1) ^ rx) << 2));
                    float4 v2 = *(const float4*)(ib + rb + (((pc + 2) ^ rx) << 2));
                    float in[12] = {v0.x, v0.y, v0.z, v0.w, v1.x, v1.y, v1.z, v1.w,
                                    v2.x, v2.y, v2.z, v2.w};
                    #pragma unroll
                    for (int kw = 0; kw < 9; kw++) {
                        acc[dy][0] = fmaf(w[kw], in[kw],     acc[dy][0]);
                        acc[dy][1] = fmaf(w[kw], in[kw + 2], acc[dy][1]);
                    }
                }
            }
        }
        float b = sm_b[oc];
        float m = fmaxf(fmaxf(acc[0][0], acc[0][1]), fmaxf(acc[1][0], acc[1][1]));
        m = fmaxf(m + b, 0.f);
        g_buf2[(n * 8 + oc) * 25 + p] = m;
        atomicAdd(&s_sum[oc], m);
        atomicAdd(&s_sq[oc], m * m);
    }
    __syncthreads();
    if (tid < 8) {
        atomicAdd(&g_stats[8 + tid],  (double)s_sum[tid]);
        atomicAdd(&g_stats[16 + tid], (double)s_sq[tid]);
    }
}

// ---------------- bn2-apply + fc stack ----------------
__global__ __launch_bounds__(256) void k_fc(
    const float* __restrict__ W1, const float* __restrict__ b1,
    const float* __restrict__ W2, const float* __restrict__ b2,
    const float* __restrict__ Wz, const float* __restrict__ bz,
    const float* __restrict__ WL, const float* __restrict__ bL,
    const float* __restrict__ g2, const float* __restrict__ be2)
{
    __shared__ float sW1[3200], sW2[512], sWz[64], sWL[96];
    __shared__ float sb1[16], sb2[32], sbz[2], sbL[3];
    __shared__ float sc[8], shh[8];
    const int tid = threadIdx.x;
    if (tid < 8) {
        double mu  = g_stats[8 + tid] * (1.0 / 20000.0);
        double var = g_stats[16 + tid] * (1.0 / 20000.0) - mu * mu;
        float scale = g2[tid] * rsqrtf((float)var + 1e-5f);
        sc[tid] = scale; shh[tid] = be2[tid] - (float)mu * scale;
    }
    for (int i = tid; i < 3200; i += 256) sW1[i] = W1[i];
    for (int i = tid; i < 512;  i += 256) sW2[i] = W2[i];
    if (tid < 64) sWz[tid] = Wz[tid];
    if (tid < 96) sWL[tid] = WL[tid];
    if (tid < 16) sb1[tid] = b1[tid];
    if (tid < 32) sb2[tid] = b2[tid];
    if (tid < 2)  sbz[tid] = bz[tid];
    if (tid < 3)  sbL[tid] = bL[tid];
    __syncthreads();

    const int lane = tid & 31;
    const int n = blockIdx.x * 8 + (tid >> 5);
    const float* src = g_buf2 + n * 200;

    float p[16];
    #pragma unroll
    for (int i = 0; i < 16; i++) p[i] = 0.f;
    #pragma unroll 1
    for (int j = lane; j < 200; j += 32) {
        int ch = j / 25;
        float fv = fmaf(src[j], sc[ch], shh[ch]);
        #pragma unroll
        for (int i = 0; i < 16; i++) p[i] = fmaf(sW1[i * 200 + j], fv, p[i]);
    }
    #pragma unroll
    for (int i = 0; i < 16; i++) {
        #pragma unroll
        for (int off = 16; off > 0; off >>= 1)
            p[i] += __shfl_xor_sync(0xffffffffu, p[i], off);
        p[i] = fmaxf(p[i] + sb1[i], 0.f);
    }
    float a = sb2[lane];
    #pragma unroll
    for (int j = 0; j < 16; j++) a = fmaf(sW2[lane * 16 + j], p[j], a);
    float f2 = fmaxf(a, 0.f);
    float v0 = sWz[lane]      * f2;
    float v1 = sWz[32 + lane] * f2;
    float v2 = sWL[lane]      * f2;
    float v3 = sWL[32 + lane] * f2;
    float v4 = sWL[64 + lane] * f2;
    #pragma unroll
    for (int off = 16; off > 0; off >>= 1) {
        v0 += __shfl_xor_sync(0xffffffffu, v0, off);
        v1 += __shfl_xor_sync(0xffffffffu, v1, off);
        v2 += __shfl_xor_sync(0xffffffffu, v2, off);
        v3 += __shfl_xor_sync(0xffffffffu, v3, off);
        v4 += __shfl_xor_sync(0xffffffffu, v4, off);
    }
    if (lane == 0) {
        g_z[n * 2]     = v0 + sbz[0];
        g_z[n * 2 + 1] = v1 + sbz[1];
        g_L[n * 3]     = v2 + sbL[0];
        g_L[n * 3 + 1] = v3 + sbL[1];
        g_L[n * 3 + 2] = v4 + sbL[2];
    }
}

// ---------------- Kalman filter: one lane per sequence ----------------
__global__ void k_kf(const float* __restrict__ Ag, const float* __restrict__ Bg,
                     const float* __restrict__ Cg, const float* __restrict__ Qg,
                     float* __restrict__ out)
{
    const int b = threadIdx.x;
    if (b >= 8) return;
    float A[16], C[8], BQBT[16], Bm[8], Q[4];
    #pragma unroll
    for (int i = 0; i < 16; i++) A[i] = Ag[i];
    #pragma unroll
    for (int i = 0; i < 8; i++)  C[i] = Cg[i];
    #pragma unroll
    for (int i = 0; i < 8; i++)  Bm[i] = Bg[i];
    #pragma unroll
    for (int i = 0; i < 4; i++)  Q[i] = Qg[i];
    #pragma unroll
    for (int i = 0; i < 4; i++) {
        float bq0 = Bm[i * 2] * Q[0] + Bm[i * 2 + 1] * Q[2];
        float bq1 = Bm[i * 2] * Q[1] + Bm[i * 2 + 1] * Q[3];
        #pragma unroll
        for (int l = 0; l < 4; l++)
            BQBT[i * 4 + l] = bq0 * Bm[l * 2] + bq1 * Bm[l * 2 + 1];
    }
    const bool cI = (C[0] == 1.f && C[1] == 0.f && C[2] == 0.f && C[3] == 0.f &&
                     C[4] == 0.f && C[5] == 1.f && C[6] == 0.f && C[7] == 0.f);
    const float* zp = g_z + b * 200;
    const float* Lp = g_L + b * 300;
    float h[4] = {zp[0], zp[1], 0.f, 0.f};
    float l0 = Lp[0], l1 = Lp[1], l2 = Lp[2];
    float s[16] = {l0 * l0, l0 * l1, 0.f, 0.f,
                   l0 * l1, l1 * l1 + l2 * l2, 0.f, 0.f,
                   0.f, 0.f, 1.f, 0.f,
                   0.f, 0.f, 0.f, 1.f};
    float* ob = out + b * 400;
    ob[0] = h[0]; ob[1] = h[1]; ob[2] = h[2]; ob[3] = h[3];

    for (int t = 1; t < 100; t++) {
        float zx = zp[t * 2], zy = zp[t * 2 + 1];
        float La = Lp[t * 3], Lb = Lp[t * 3 + 1], Lc = Lp[t * 3 + 2];
        float r00 = La * La, r01 = La * Lb, r11 = Lb * Lb + Lc * Lc;
        float hp[4];
        #pragma unroll
        for (int i = 0; i < 4; i++)
            hp[i] = A[i*4]*h[0] + A[i*4+1]*h[1] + A[i*4+2]*h[2] + A[i*4+3]*h[3];
        float tmp[16];
        #pragma unroll
        for (int i = 0; i < 4; i++)
            #pragma unroll
            for (int k = 0; k < 4; k++)
                tmp[i*4+k] = A[i*4]*s[k] + A[i*4+1]*s[4+k] + A[i*4+2]*s[8+k] + A[i*4+3]*s[12+k];
        float sp[16];
        #pragma unroll
        for (int i = 0; i < 4; i++)
            #pragma unroll
            for (int l = 0; l < 4; l++)
                sp[i*4+l] = BQBT[i*4+l] + tmp[i*4]*A[l*4] + tmp[i*4+1]*A[l*4+1]
                          + tmp[i*4+2]*A[l*4+2] + tmp[i*4+3]*A[l*4+3];
        if (cI) {
            float S00 = sp[0] + r00, S01 = sp[1] + r01;
            float S10 = sp[4] + r01, S11 = sp[5] + r11;
            float idet = 1.f / (S00 * S11 - S01 * S10);
            float Si00 = S11 * idet, Si01 = -S01 * idet;
            float Si10 = -S10 * idet, Si11 = S00 * idet;
            float K[8];
            #pragma unroll
            for (int i = 0; i < 4; i++) {
                K[i*2]   = sp[i*4]*Si00 + sp[i*4+1]*Si10;
                K[i*2+1] = sp[i*4]*Si01 + sp[i*4+1]*Si11;
            }
            float a0 = zx - hp[0];
            float a1 = zy - hp[1];
            #pragma unroll
            for (int i = 0; i < 4; i++) h[i] = hp[i] + K[i*2]*a0 + K[i*2+1]*a1;
            #pragma unroll
            for (int i = 0; i < 4; i++)
                #pragma unroll
                for (int l = 0; l < 4; l++)
                    s[i*4+l] = sp[i*4+l] - K[i*2]*sp[l] - K[i*2+1]*sp[4+l];
        } else {
            float sct[8];
            #pragma unroll
            for (int i = 0; i < 4; i++)
                #pragma unroll
                for (int j = 0; j < 2; j++)
                    sct[i*2+j] = sp[i*4]*C[j*4] + sp[i*4+1]*C[j*4+1]
                               + sp[i*4+2]*C[j*4+2] + sp[i*4+3]*C[j*4+3];
            float S00 = C[0]*sct[0] + C[1]*sct[2] + C[2]*sct[4] + C[3]*sct[6] + r00;
            float S01 = C[0]*sct[1] + C[1]*sct[3] + C[2]*sct[5] + C[3]*sct[7] + r01;
            float S10 = C[4]*sct[0] + C[5]*sct[2] + C[6]*sct[4] + C[7]*sct[6] + r01;
            float S11 = C[4]*sct[1] + C[5]*sct[3] + C[6]*sct[5] + C[7]*sct[7] + r11;
            float idet = 1.f / (S00 * S11 - S01 * S10);
            float Si00 = S11 * idet, Si01 = -S01 * idet, Si10 = -S10 * idet, Si11 = S00 * idet;
            float K[8];
            #pragma unroll
            for (int i = 0; i < 4; i++) {
                K[i*2]   = sct[i*2]*Si00 + sct[i*2+1]*Si10;
                K[i*2+1] = sct[i*2]*Si01 + sct[i*2+1]*Si11;
            }
            float a0 = zx - (C[0]*hp[0] + C[1]*hp[1] + C[2]*hp[2] + C[3]*hp[3]);
            float a1 = zy - (C[4]*hp[0] + C[5]*hp[1] + C[6]*hp[2] + C[7]*hp[3]);
            #pragma unroll
            for (int i = 0; i < 4; i++) h[i] = hp[i] + K[i*2]*a0 + K[i*2+1]*a1;
            float M[16];
            #pragma unroll
            for (int i = 0; i < 4; i++)
                #pragma unroll
                for (int j = 0; j < 4; j++)
                    M[i*4+j] = (i == j ? 1.f : 0.f) - (K[i*2]*C[j] + K[i*2+1]*C[4+j]);
            #pragma unroll
            for (int i = 0; i < 4; i++)
                #pragma unroll
                for (int l = 0; l < 4; l++)
                    s[i*4+l] = M[i*4]*sp[l] + M[i*4+1]*sp[4+l]
                             + M[i*4+2]*sp[8+l] + M[i*4+3]*sp[12+l];
        }
        ob[t*4]   = h[0]; ob[t*4+1] = h[1];
        ob[t*4+2] = h[2]; ob[t*4+3] = h[3];
    }
}

extern "C" void kernel_launch(void* const* d_in, const int* in_sizes, int n_in,
                              void* d_out, int out_size) {
    const float* x    = (const float*)d_in[0];
    const float* c1w  = (const float*)d_in[1];
    const float* c1b  = (const float*)d_in[2];
    const float* bn1g = (const float*)d_in[3];
    const float* bn1b = (const float*)d_in[4];
    const float* c2w  = (const float*)d_in[5];
    const float* c2b  = (const float*)d_in[6];
    const float* bn2g = (const float*)d_in[7];
    const float* bn2b = (const float*)d_in[8];
    const float* W1   = (const float*)d_in[9];
    const float* b1   = (const float*)d_in[10];
    const float* W2   = (const float*)d_in[11];
    const float* b2   = (const float*)d_in[12];
    const float* Wz   = (const float*)d_in[13];
    const float* bz   = (const float*)d_in[14];
    const float* WL   = (const float*)d_in[15];
    const float* bL   = (const float*)d_in[16];
    const float* A    = (const float*)d_in[17];
    const float* B    = (const float*)d_in[18];
    const float* C    = (const float*)d_in[19];
    const float* Q    = (const float*)d_in[20];
    float* out = (float*)d_out;

    static int attr_done = 0;
    if (!attr_done) {
        cudaFuncSetAttribute(k_conv1, cudaFuncAttributeMaxDynamicSharedMemorySize, C1_DSM);
        attr_done = 1;
    }

    k_zero<<<1, 32>>>();
    k_conv1<<<dim3(3, 800), 160, C1_DSM>>>(x, c1w, c1b);
    k_conv2<<<800, 224>>>(c2w, c2b, bn1g, bn1b);
    k_fc<<<100, 256>>>(W1, b1, W2, b2, Wz, bz, WL, bL, bn2g, bn2b);
    k_kf<<<1, 32>>>(A, B, C, Q, out);
}

// round 5
// speedup vs baseline: 1.2805x; 1.2805x over previous
#include <cuda_runtime.h>

#define NIMG 800

// ---------------- scratch (no allocation allowed) ----------------
__device__ float  g_buf1[NIMG * 4 * 30 * 30];   // conv1 pooled output (NCHW)
__device__ float  g_buf2[NIMG * 8 * 25];        // conv2 pooled output (NCHW)
__device__ float  g_z[NIMG * 2];
__device__ float  g_L[NIMG * 3];
__device__ double g_stats[24];  // [0:4) bn1 sum, [4:8) bn1 sumsq, [8:16) bn2 sum, [16:24) bn2 sumsq

__global__ void k_zero() { if (threadIdx.x < 24) g_stats[threadIdx.x] = 0.0; }

// ---- f32x2 packed-math helpers ----
__device__ __forceinline__ unsigned long long ffma2(unsigned long long a,
                                                    unsigned long long b,
                                                    unsigned long long c) {
    unsigned long long d;
    asm("fma.rn.f32x2 %0, %1, %2, %3;" : "=l"(d) : "l"(a), "l"(b), "l"(c));
    return d;
}
__device__ __forceinline__ unsigned long long packbc(float x) {  // (x, x)
    unsigned long long d;
    asm("mov.b64 %0, {%1, %2};" : "=l"(d) : "f"(x), "f"(x));
    return d;
}
__device__ __forceinline__ void unpack2(unsigned long long v, float& lo, float& hi) {
    asm("mov.b64 {%0, %1}, %2;" : "=f"(lo), "=f"(hi) : "l"(v));
}

// ---------------- conv1 + bias + relu + maxpool2 + bn1-stats (R3 version) ----------------
__global__ __launch_bounds__(160) void k_conv1(
    const float* __restrict__ x, const float* __restrict__ cw,
    const float* __restrict__ cb)
{
    __shared__ __align__(16) float sm_in[3 * 3460];  // planar [3][27][128], plane stride 3460
    __shared__ __align__(16) float sm_w[972];        // [ic][kh][kw][oc]
    __shared__ float sm_b[4];
    __shared__ float s_part[5][8];
    const int tid = threadIdx.x;
    const int n   = blockIdx.y;
    const int r0  = blockIdx.x * 5;

    if (tid < 4) sm_b[tid] = cb[tid];
    for (int i = tid; i < 972; i += 160) {
        int oc = i & 3; int rest = i >> 2;
        int kw = rest % 9; int t2 = rest / 9; int kh = t2 % 9; int ic = t2 / 9;
        sm_w[i] = cw[oc * 243 + ic * 81 + kh * 9 + kw];
    }
    const float4* xb = (const float4*)(x + (size_t)n * 49152 + (size_t)r0 * 1536);
    for (int i = tid; i < 864; i += 160) {            // 27 rows x 32 groups
        int row = i >> 5; int g = i & 31;
        const float4* src = xb + row * 96 + g * 3;
        float4 a = src[0], b = src[1], c = src[2];
        int base = row * 128 + 4 * g;
        *(float4*)(sm_in + base)            = make_float4(a.x, a.w, b.z, c.y);
        *(float4*)(sm_in + 3460 + base)     = make_float4(a.y, b.x, b.w, c.z);
        *(float4*)(sm_in + 6920 + base)     = make_float4(a.z, b.y, c.x, c.w);
    }
    __syncthreads();

    const bool valid = (tid < 150);
    const int pw  = tid % 30;
    const int phl = valid ? (tid / 30) : 4;

    unsigned long long acc[2][2][2];
    #pragma unroll
    for (int p = 0; p < 2; p++)
        #pragma unroll
        for (int dy = 0; dy < 2; dy++) { acc[p][dy][0] = 0ull; acc[p][dy][1] = 0ull; }

    #pragma unroll 1
    for (int ic = 0; ic < 3; ic++) {
        const float* pl = sm_in + ic * 3460 + phl * 512 + pw * 4;
        const float* wb = sm_w + ic * 324;
        #pragma unroll 1
        for (int kh = 0; kh < 9; kh++) {
            unsigned long long bpa[11], bpb[11];
            {
                const float* rp = pl + kh * 128;
                float4 va = *(const float4*)(rp);
                float4 vb = *(const float4*)(rp + 4);
                float4 vc = *(const float4*)(rp + 8);
                float in[12] = {va.x, va.y, va.z, va.w, vb.x, vb.y, vb.z, vb.w,
                                vc.x, vc.y, vc.z, vc.w};
                #pragma unroll
                for (int j = 0; j < 11; j++) bpa[j] = packbc(in[j]);
            }
            {
                const float* rp = pl + (kh + 2) * 128;
                float4 va = *(const float4*)(rp);
                float4 vb = *(const float4*)(rp + 4);
                float4 vc = *(const float4*)(rp + 8);
                float in[12] = {va.x, va.y, va.z, va.w, vb.x, vb.y, vb.z, vb.w,
                                vc.x, vc.y, vc.z, vc.w};
                #pragma unroll
                for (int j = 0; j < 11; j++) bpb[j] = packbc(in[j]);
            }
            #pragma unroll
            for (int kw = 0; kw < 9; kw++) {
                ulonglong2 w2 = *(const ulonglong2*)(wb + (kh * 9 + kw) * 4);
                acc[0][0][0] = ffma2(w2.x, bpa[kw],     acc[0][0][0]);
                acc[0][0][1] = ffma2(w2.x, bpa[kw + 2], acc[0][0][1]);
                acc[1][0][0] = ffma2(w2.y, bpa[kw],     acc[1][0][0]);
                acc[1][0][1] = ffma2(w2.y, bpa[kw + 2], acc[1][0][1]);
                acc[0][1][0] = ffma2(w2.x, bpb[kw],     acc[0][1][0]);
                acc[0][1][1] = ffma2(w2.x, bpb[kw + 2], acc[0][1][1]);
                acc[1][1][0] = ffma2(w2.y, bpb[kw],     acc[1][1][0]);
                acc[1][1][1] = ffma2(w2.y, bpb[kw + 2], acc[1][1][1]);
            }
        }
    }
    float m4[4];
    #pragma unroll
    for (int p = 0; p < 2; p++) {
        float l00, h00, l01, h01, l10, h10, l11, h11;
        unpack2(acc[p][0][0], l00, h00);
        unpack2(acc[p][0][1], l01, h01);
        unpack2(acc[p][1][0], l10, h10);
        unpack2(acc[p][1][1], l11, h11);
        m4[2 * p]     = fmaxf(fmaxf(l00, l01), fmaxf(l10, l11));
        m4[2 * p + 1] = fmaxf(fmaxf(h00, h01), fmaxf(h10, h11));
    }
    const int ph = r0 + phl;
    float vs[4], vq[4];
    #pragma unroll
    for (int oc = 0; oc < 4; oc++) {
        float m = fmaxf(m4[oc] + sm_b[oc], 0.f);
        if (valid) g_buf1[((n * 4 + oc) * 30 + ph) * 30 + pw] = m;
        vs[oc] = valid ? m : 0.f;
        vq[oc] = valid ? m * m : 0.f;
    }
    #pragma unroll
    for (int oc = 0; oc < 4; oc++)
        #pragma unroll
        for (int off = 16; off > 0; off >>= 1) {
            vs[oc] += __shfl_xor_sync(0xffffffffu, vs[oc], off);
            vq[oc] += __shfl_xor_sync(0xffffffffu, vq[oc], off);
        }
    const int wp = tid >> 5;
    if ((tid & 31) == 0) {
        #pragma unroll
        for (int oc = 0; oc < 4; oc++) {
            s_part[wp][oc]     = vs[oc];
            s_part[wp][4 + oc] = vq[oc];
        }
    }
    __syncthreads();
    if (tid < 8) {
        float t = 0.f;
        #pragma unroll
        for (int w = 0; w < 5; w++) t += s_part[w][tid];
        atomicAdd(&g_stats[tid], (double)t);
    }
}

// ---------------- bn1-apply + conv2 + relu + pool + bn2-stats ----------------
// Block: 8 images x 25 positions (+pad). Thread: 1 position, ALL 8 oc (4 FFMA2 pairs).
#define C2_IS  3844                      // per-image smem stride (floats); +4 de-conflicts images
#define C2_DSM (8 * C2_IS * 4)           // 123,008 bytes dynamic smem

__global__ __launch_bounds__(224) void k_conv2(
    const float* __restrict__ cw, const float* __restrict__ cb,
    const float* __restrict__ g1, const float* __restrict__ b1)
{
    extern __shared__ __align__(16) float c2sm[];
    __shared__ __align__(16) float sm_w[2592];   // [(ic*9+kh)*9+kw]*8 + oc
    __shared__ float sm_b[8];
    __shared__ float sc[4], shh[4];
    __shared__ float s_part[7][16];
    const int tid = threadIdx.x;
    const int n0  = blockIdx.x * 8;

    if (tid < 4) {
        double mu  = g_stats[tid] * (1.0 / 720000.0);
        double var = g_stats[4 + tid] * (1.0 / 720000.0) - mu * mu;
        float scale = g1[tid] * rsqrtf((float)var + 1e-5f);
        sc[tid] = scale; shh[tid] = b1[tid] - (float)mu * scale;
    }
    if (tid < 8) sm_b[tid] = cb[tid];
    for (int i = tid; i < 2592; i += 224) {
        int oc = i & 7; int rest = i >> 3;
        int kw = rest % 9; int t2 = rest / 9; int kh = t2 % 9; int ic = t2 / 9;
        sm_w[i] = cw[oc * 324 + ic * 81 + kh * 9 + kw];
    }
    __syncthreads();   // sc/shh ready for staging

    {
        int img = tid / 25;
        int l25 = tid - img * 25;
        if (img < 8) {
            const float* srcp = g_buf1 + (size_t)(n0 + img) * 3600;
            float* dimg = c2sm + img * C2_IS;
            int ic = 0, row = 0, col = l25;
            for (int i = l25; i < 3600; i += 25) {
                float v = fmaf(srcp[i], sc[ic], shh[ic]);
                int chunk = col >> 2, within = col & 3;
                dimg[ic * 960 + row * 32 + (((chunk ^ (row & 7)) << 2) | within)] = v;
                col += 25;
                if (col >= 30) { col -= 30; row++; if (row >= 30) { row = 0; ic++; } }
            }
        }
    }
    __syncthreads();

    const bool valid = (tid < 200);
    const int img = valid ? (tid / 25) : 7;
    const int l25 = tid % 25;
    const int pr = l25 / 5, pc = l25 - pr * 5;

    unsigned long long acc[4][2][2];
    #pragma unroll
    for (int q = 0; q < 4; q++)
        #pragma unroll
        for (int dy = 0; dy < 2; dy++) { acc[q][dy][0] = 0ull; acc[q][dy][1] = 0ull; }

    const float* ib0 = c2sm + img * C2_IS;
    #pragma unroll 1
    for (int ic = 0; ic < 4; ic++) {
        const float* ib = ib0 + ic * 960;
        const float* wb = sm_w + ic * 648;
        #pragma unroll 1
        for (int kh = 0; kh < 9; kh++) {
            unsigned long long bpa[11], bpb[11];
            {
                int row = 4 * pr + kh;
                int rb = row * 32, rx = row & 7;
                float4 v0 = *(const float4*)(ib + rb + (((pc    ) ^ rx) << 2));
                float4 v1 = *(const float4*)(ib + rb + (((pc + 1) ^ rx) << 2));
                float4 v2 = *(const float4*)(ib + rb + (((pc + 2) ^ rx) << 2));
                float in[12] = {v0.x, v0.y, v0.z, v0.w, v1.x, v1.y, v1.z, v1.w,
                                v2.x, v2.y, v2.z, v2.w};
                #pragma unroll
                for (int j = 0; j < 11; j++) bpa[j] = packbc(in[j]);
            }
            {
                int row = 4 * pr + kh + 2;
                int rb = row * 32, rx = row & 7;
                float4 v0 = *(const float4*)(ib + rb + (((pc    ) ^ rx) << 2));
                float4 v1 = *(const float4*)(ib + rb + (((pc + 1) ^ rx) << 2));
                float4 v2 = *(const float4*)(ib + rb + (((pc + 2) ^ rx) << 2));
                float in[12] = {v0.x, v0.y, v0.z, v0.w, v1.x, v1.y, v1.z, v1.w,
                                v2.x, v2.y, v2.z, v2.w};
                #pragma unroll
                for (int j = 0; j < 11; j++) bpb[j] = packbc(in[j]);
            }
            #pragma unroll
            for (int kw = 0; kw < 9; kw++) {
                ulonglong2 wlo = *(const ulonglong2*)(wb + (kh * 9 + kw) * 8);
                ulonglong2 whi = *(const ulonglong2*)(wb + (kh * 9 + kw) * 8 + 4);
                acc[0][0][0] = ffma2(wlo.x, bpa[kw],     acc[0][0][0]);
                acc[0][0][1] = ffma2(wlo.x, bpa[kw + 2], acc[0][0][1]);
                acc[1][0][0] = ffma2(wlo.y, bpa[kw],     acc[1][0][0]);
                acc[1][0][1] = ffma2(wlo.y, bpa[kw + 2], acc[1][0][1]);
                acc[2][0][0] = ffma2(whi.x, bpa[kw],     acc[2][0][0]);
                acc[2][0][1] = ffma2(whi.x, bpa[kw + 2], acc[2][0][1]);
                acc[3][0][0] = ffma2(whi.y, bpa[kw],     acc[3][0][0]);
                acc[3][0][1] = ffma2(whi.y, bpa[kw + 2], acc[3][0][1]);
                acc[0][1][0] = ffma2(wlo.x, bpb[kw],     acc[0][1][0]);
                acc[0][1][1] = ffma2(wlo.x, bpb[kw + 2], acc[0][1][1]);
                acc[1][1][0] = ffma2(wlo.y, bpb[kw],     acc[1][1][0]);
                acc[1][1][1] = ffma2(wlo.y, bpb[kw + 2], acc[1][1][1]);
                acc[2][1][0] = ffma2(whi.x, bpb[kw],     acc[2][1][0]);
                acc[2][1][1] = ffma2(whi.x, bpb[kw + 2], acc[2][1][1]);
                acc[3][1][0] = ffma2(whi.y, bpb[kw],     acc[3][1][0]);
                acc[3][1][1] = ffma2(whi.y, bpb[kw + 2], acc[3][1][1]);
            }
        }
    }
    float vs[8], vq[8];
    #pragma unroll
    for (int q = 0; q < 4; q++) {
        float l00, h00, l01, h01, l10, h10, l11, h11;
        unpack2(acc[q][0][0], l00, h00);
        unpack2(acc[q][0][1], l01, h01);
        unpack2(acc[q][1][0], l10, h10);
        unpack2(acc[q][1][1], l11, h11);
        float mlo = fmaxf(fmaxf(l00, l01), fmaxf(l10, l11));
        float mhi = fmaxf(fmaxf(h00, h01), fmaxf(h10, h11));
        float a0 = fmaxf(mlo + sm_b[2 * q],     0.f);
        float a1 = fmaxf(mhi + sm_b[2 * q + 1], 0.f);
        if (valid) {
            g_buf2[((n0 + img) * 8 + 2 * q)     * 25 + l25] = a0;
            g_buf2[((n0 + img) * 8 + 2 * q + 1) * 25 + l25] = a1;
        }
        vs[2 * q]     = valid ? a0 : 0.f;
        vs[2 * q + 1] = valid ? a1 : 0.f;
        vq[2 * q]     = valid ? a0 * a0 : 0.f;
        vq[2 * q + 1] = valid ? a1 * a1 : 0.f;
    }
    #pragma unroll
    for (int oc = 0; oc < 8; oc++)
        #pragma unroll
        for (int off = 16; off > 0; off >>= 1) {
            vs[oc] += __shfl_xor_sync(0xffffffffu, vs[oc], off);
            vq[oc] += __shfl_xor_sync(0xffffffffu, vq[oc], off);
        }
    const int wp = tid >> 5;
    if ((tid & 31) == 0) {
        #pragma unroll
        for (int oc = 0; oc < 8; oc++) {
            s_part[wp][oc]     = vs[oc];
            s_part[wp][8 + oc] = vq[oc];
        }
    }
    __syncthreads();
    if (tid < 16) {
        float t = 0.f;
        #pragma unroll
        for (int w = 0; w < 7; w++) t += s_part[w][tid];
        atomicAdd(&g_stats[8 + tid], (double)t);   // tid<8 -> sum [8:16), tid>=8 -> sq [16:24)
    }
}

// ---------------- bn2-apply + fc stack ----------------
__global__ __launch_bounds__(256) void k_fc(
    const float* __restrict__ W1, const float* __restrict__ b1,
    const float* __restrict__ W2, const float* __restrict__ b2,
    const float* __restrict__ Wz, const float* __restrict__ bz,
    const float* __restrict__ WL, const float* __restrict__ bL,
    const float* __restrict__ g2, const float* __restrict__ be2)
{
    __shared__ float sW1[3200], sW2[512], sWz[64], sWL[96];
    __shared__ float sb1[16], sb2[32], sbz[2], sbL[3];
    __shared__ float sc[8], shh[8];
    const int tid = threadIdx.x;
    if (tid < 8) {
        double mu  = g_stats[8 + tid] * (1.0 / 20000.0);
        double var = g_stats[16 + tid] * (1.0 / 20000.0) - mu * mu;
        float scale = g2[tid] * rsqrtf((float)var + 1e-5f);
        sc[tid] = scale; shh[tid] = be2[tid] - (float)mu * scale;
    }
    for (int i = tid; i < 3200; i += 256) sW1[i] = W1[i];
    for (int i = tid; i < 512;  i += 256) sW2[i] = W2[i];
    if (tid < 64) sWz[tid] = Wz[tid];
    if (tid < 96) sWL[tid] = WL[tid];
    if (tid < 16) sb1[tid] = b1[tid];
    if (tid < 32) sb2[tid] = b2[tid];
    if (tid < 2)  sbz[tid] = bz[tid];
    if (tid < 3)  sbL[tid] = bL[tid];
    __syncthreads();

    const int lane = tid & 31;
    const int n = blockIdx.x * 8 + (tid >> 5);
    const float* src = g_buf2 + n * 200;

    float p[16];
    #pragma unroll
    for (int i = 0; i < 16; i++) p[i] = 0.f;
    #pragma unroll
    for (int k = 0; k < 7; k++) {
        int j = lane + 32 * k;
        if (j < 200) {
            int ch = j / 25;
            float fv = fmaf(src[j], sc[ch], shh[ch]);
            #pragma unroll
            for (int i = 0; i < 16; i++) p[i] = fmaf(sW1[i * 200 + j], fv, p[i]);
        }
    }
    #pragma unroll
    for (int i = 0; i < 16; i++) {
        #pragma unroll
        for (int off = 16; off > 0; off >>= 1)
            p[i] += __shfl_xor_sync(0xffffffffu, p[i], off);
        p[i] = fmaxf(p[i] + sb1[i], 0.f);
    }
    float a = sb2[lane];
    #pragma unroll
    for (int j = 0; j < 16; j++) a = fmaf(sW2[lane * 16 + j], p[j], a);
    float f2 = fmaxf(a, 0.f);
    float v0 = sWz[lane]      * f2;
    float v1 = sWz[32 + lane] * f2;
    float v2 = sWL[lane]      * f2;
    float v3 = sWL[32 + lane] * f2;
    float v4 = sWL[64 + lane] * f2;
    #pragma unroll
    for (int off = 16; off > 0; off >>= 1) {
        v0 += __shfl_xor_sync(0xffffffffu, v0, off);
        v1 += __shfl_xor_sync(0xffffffffu, v1, off);
        v2 += __shfl_xor_sync(0xffffffffu, v2, off);
        v3 += __shfl_xor_sync(0xffffffffu, v3, off);
        v4 += __shfl_xor_sync(0xffffffffu, v4, off);
    }
    if (lane == 0) {
        g_z[n * 2]     = v0 + sbz[0];
        g_z[n * 2 + 1] = v1 + sbz[1];
        g_L[n * 3]     = v2 + sbL[0];
        g_L[n * 3 + 1] = v3 + sbL[1];
        g_L[n * 3 + 2] = v4 + sbL[2];
    }
}

// ---------------- Kalman filter: one lane per sequence, z/L prefetched ----------------
__global__ void k_kf(const float* __restrict__ Ag, const float* __restrict__ Bg,
                     const float* __restrict__ Cg, const float* __restrict__ Qg,
                     float* __restrict__ out)
{
    const int b = threadIdx.x;
    if (b >= 8) return;
    float A[16], C[8], BQBT[16], Bm[8], Q[4];
    #pragma unroll
    for (int i = 0; i < 16; i++) A[i] = Ag[i];
    #pragma unroll
    for (int i = 0; i < 8; i++)  C[i] = Cg[i];
    #pragma unroll
    for (int i = 0; i < 8; i++)  Bm[i] = Bg[i];
    #pragma unroll
    for (int i = 0; i < 4; i++)  Q[i] = Qg[i];
    #pragma unroll
    for (int i = 0; i < 4; i++) {
        float bq0 = Bm[i * 2] * Q[0] + Bm[i * 2 + 1] * Q[2];
        float bq1 = Bm[i * 2] * Q[1] + Bm[i * 2 + 1] * Q[3];
        #pragma unroll
        for (int l = 0; l < 4; l++)
            BQBT[i * 4 + l] = bq0 * Bm[l * 2] + bq1 * Bm[l * 2 + 1];
    }
    const bool cI = (C[0] == 1.f && C[1] == 0.f && C[2] == 0.f && C[3] == 0.f &&
                     C[4] == 0.f && C[5] == 1.f && C[6] == 0.f && C[7] == 0.f);
    const float* zp = g_z + b * 200;
    const float* Lp = g_L + b * 300;
    float h[4] = {zp[0], zp[1], 0.f, 0.f};
    float l0 = Lp[0], l1 = Lp[1], l2 = Lp[2];
    float s[16] = {l0 * l0, l0 * l1, 0.f, 0.f,
                   l0 * l1, l1 * l1 + l2 * l2, 0.f, 0.f,
                   0.f, 0.f, 1.f, 0.f,
                   0.f, 0.f, 0.f, 1.f};
    float* ob = out + b * 400;
    *(float4*)ob = make_float4(h[0], h[1], h[2], h[3]);

    float nzx = zp[2], nzy = zp[3];
    float nLa = Lp[3], nLb = Lp[4], nLc = Lp[5];

    for (int t = 1; t < 100; t++) {
        float zx = nzx, zy = nzy;
        float La = nLa, Lb = nLb, Lc = nLc;
        if (t < 99) {
            nzx = zp[(t + 1) * 2];     nzy = zp[(t + 1) * 2 + 1];
            nLa = Lp[(t + 1) * 3];     nLb = Lp[(t + 1) * 3 + 1];
            nLc = Lp[(t + 1) * 3 + 2];
        }
        float r00 = La * La, r01 = La * Lb, r11 = Lb * Lb + Lc * Lc;
        float hp[4];
        #pragma unroll
        for (int i = 0; i < 4; i++)
            hp[i] = A[i*4]*h[0] + A[i*4+1]*h[1] + A[i*4+2]*h[2] + A[i*4+3]*h[3];
        float tmp[16];
        #pragma unroll
        for (int i = 0; i < 4; i++)
            #pragma unroll
            for (int k = 0; k < 4; k++)
                tmp[i*4+k] = A[i*4]*s[k] + A[i*4+1]*s[4+k] + A[i*4+2]*s[8+k] + A[i*4+3]*s[12+k];
        float sp[16];
        #pragma unroll
        for (int i = 0; i < 4; i++)
            #pragma unroll
            for (int l = 0; l < 4; l++)
                sp[i*4+l] = BQBT[i*4+l] + tmp[i*4]*A[l*4] + tmp[i*4+1]*A[l*4+1]
                          + tmp[i*4+2]*A[l*4+2] + tmp[i*4+3]*A[l*4+3];
        if (cI) {
            float S00 = sp[0] + r00, S01 = sp[1] + r01;
            float S10 = sp[4] + r01, S11 = sp[5] + r11;
            float idet = 1.f / (S00 * S11 - S01 * S10);
            float Si00 = S11 * idet, Si01 = -S01 * idet;
            float Si10 = -S10 * idet, Si11 = S00 * idet;
            float K[8];
            #pragma unroll
            for (int i = 0; i < 4; i++) {
                K[i*2]   = sp[i*4]*Si00 + sp[i*4+1]*Si10;
                K[i*2+1] = sp[i*4]*Si01 + sp[i*4+1]*Si11;
            }
            float a0 = zx - hp[0];
            float a1 = zy - hp[1];
            #pragma unroll
            for (int i = 0; i < 4; i++) h[i] = hp[i] + K[i*2]*a0 + K[i*2+1]*a1;
            #pragma unroll
            for (int i = 0; i < 4; i++)
                #pragma unroll
                for (int l = 0; l < 4; l++)
                    s[i*4+l] = sp[i*4+l] - K[i*2]*sp[l] - K[i*2+1]*sp[4+l];
        } else {
            float sct[8];
            #pragma unroll
            for (int i = 0; i < 4; i++)
                #pragma unroll
                for (int j = 0; j < 2; j++)
                    sct[i*2+j] = sp[i*4]*C[j*4] + sp[i*4+1]*C[j*4+1]
                               + sp[i*4+2]*C[j*4+2] + sp[i*4+3]*C[j*4+3];
            float S00 = C[0]*sct[0] + C[1]*sct[2] + C[2]*sct[4] + C[3]*sct[6] + r00;
            float S01 = C[0]*sct[1] + C[1]*sct[3] + C[2]*sct[5] + C[3]*sct[7] + r01;
            float S10 = C[4]*sct[0] + C[5]*sct[2] + C[6]*sct[4] + C[7]*sct[6] + r01;
            float S11 = C[4]*sct[1] + C[5]*sct[3] + C[6]*sct[5] + C[7]*sct[7] + r11;
            float idet = 1.f / (S00 * S11 - S01 * S10);
            float Si00 = S11 * idet, Si01 = -S01 * idet, Si10 = -S10 * idet, Si11 = S00 * idet;
            float K[8];
            #pragma unroll
            for (int i = 0; i < 4; i++) {
                K[i*2]   = sct[i*2]*Si00 + sct[i*2+1]*Si10;
                K[i*2+1] = sct[i*2]*Si01 + sct[i*2+1]*Si11;
            }
            float a0 = zx - (C[0]*hp[0] + C[1]*hp[1] + C[2]*hp[2] + C[3]*hp[3]);
            float a1 = zy - (C[4]*hp[0] + C[5]*hp[1] + C[6]*hp[2] + C[7]*hp[3]);
            #pragma unroll
            for (int i = 0; i < 4; i++) h[i] = hp[i] + K[i*2]*a0 + K[i*2+1]*a1;
            float M[16];
            #pragma unroll
            for (int i = 0; i < 4; i++)
                #pragma unroll
                for (int j = 0; j < 4; j++)
                    M[i*4+j] = (i == j ? 1.f : 0.f) - (K[i*2]*C[j] + K[i*2+1]*C[4+j]);
            #pragma unroll
            for (int i = 0; i < 4; i++)
                #pragma unroll
                for (int l = 0; l < 4; l++)
                    s[i*4+l] = M[i*4]*sp[l] + M[i*4+1]*sp[4+l]
                             + M[i*4+2]*sp[8+l] + M[i*4+3]*sp[12+l];
        }
        *(float4*)(ob + t * 4) = make_float4(h[0], h[1], h[2], h[3]);
    }
}

extern "C" void kernel_launch(void* const* d_in, const int* in_sizes, int n_in,
                              void* d_out, int out_size) {
    const float* x    = (const float*)d_in[0];
    const float* c1w  = (const float*)d_in[1];
    const float* c1b  = (const float*)d_in[2];
    const float* bn1g = (const float*)d_in[3];
    const float* bn1b = (const float*)d_in[4];
    const float* c2w  = (const float*)d_in[5];
    const float* c2b  = (const float*)d_in[6];
    const float* bn2g = (const float*)d_in[7];
    const float* bn2b = (const float*)d_in[8];
    const float* W1   = (const float*)d_in[9];
    const float* b1   = (const float*)d_in[10];
    const float* W2   = (const float*)d_in[11];
    const float* b2   = (const float*)d_in[12];
    const float* Wz   = (const float*)d_in[13];
    const float* bz   = (const float*)d_in[14];
    const float* WL   = (const float*)d_in[15];
    const float* bL   = (const float*)d_in[16];
    const float* A    = (const float*)d_in[17];
    const float* B    = (const float*)d_in[18];
    const float* C    = (const float*)d_in[19];
    const float* Q    = (const float*)d_in[20];
    float* out = (float*)d_out;

    static int attr_done = 0;
    if (!attr_done) {
        cudaFuncSetAttribute(k_conv2, cudaFuncAttributeMaxDynamicSharedMemorySize, C2_DSM);
        attr_done = 1;
    }

    k_zero<<<1, 32>>>();
    k_conv1<<<dim3(6, 800), 160>>>(x, c1w, c1b);
    k_conv2<<<100, 224, C2_DSM>>>(c2w, c2b, bn1g, bn1b);
    k_fc<<<100, 256>>>(W1, b1, W2, b2, Wz, bz, WL, bL, bn2g, bn2b);
    k_kf<<<1, 32>>>(A, B, C, Q, out);
}